// round 11
// baseline (speedup 1.0000x reference)
#include <cuda_runtime.h>
#include <cuda_bf16.h>
#include <math.h>
#include <stdint.h>

#define Bb   16
#define HWd  4096
#define Dd   512
#define CLd  768
#define Kch  512
#define Vch  512
#define NLd  32
#define Hh   8
#define Mm   (Bb*HWd)
#define SPL  8

// ---------------- scratch ----------------
static __device__ float g_vis[(size_t)Mm*Dd];
static __device__ float g_q  [(size_t)Mm*Kch];
static __device__ float g_lv [(size_t)Mm*CLd];
static __device__ float g_vo [(size_t)Mm*Vch];
static __device__ float g_sim[(size_t)Bb*Hh*HWd*NLd];
static __device__ __nv_bfloat16 g_xh[(size_t)Mm*Dd],  g_xl[(size_t)Mm*Dd];
static __device__ __nv_bfloat16 g_ath[(size_t)Mm*Vch], g_atl[(size_t)Mm*Vch];
static __device__ __nv_bfloat16 g_zh[(size_t)Mm*Vch],  g_zl[(size_t)Mm*Vch];
#define WOFF_VIS 0
#define WOFF_Q   262144
#define WOFF_LV  524288
#define WOFF_W   917504
#define WOFF_MM  1179648
static __device__ __nv_bfloat16 g_wh[1441792], g_wl[1441792];
static __device__ float g_lang[Bb*CLd*NLd];
static __device__ float g_k  [Bb*Kch*NLd];
static __device__ float g_v  [Bb*Vch*NLd];
static __device__ float g_lop[SPL][Bb*CLd*NLd];
static __device__ float g_lo1[Bb*CLd*NLd];
static __device__ float g_lo2[Bb*CLd*NLd];
static __device__ float g_zt [Bb*CLd*NLd];
static __device__ float g_mq [Bb*Kch],  g_rq [Bb*Kch];
static __device__ float g_mlv[Bb*CLd],  g_rlv[Bb*CLd];
static __device__ float g_mw [Bb*Vch],  g_rw [Bb*Vch];
static __device__ float g_lmax[Bb*Hh*NLd], g_lsum[Bb*Hh*NLd];

__device__ __forceinline__ float gelu_f(float x){
    return 0.5f*x*(1.0f + erff(x*0.70710678118654752f));
}
__device__ __forceinline__ uint32_t smem_u32(const void* p){
    uint32_t a;
    asm("{ .reg .u64 t; cvta.to.shared.u64 t, %1; cvt.u32.u64 %0, t; }" : "=r"(a) : "l"(p));
    return a;
}
__device__ __forceinline__ void cp16(uint32_t s, const void* g){
    asm volatile("cp.async.cg.shared.global [%0], [%1], 16;" :: "r"(s), "l"(g));
}
__device__ __forceinline__ void mma16816(float* c, const uint32_t* a, const uint32_t* b){
    asm volatile("mma.sync.aligned.m16n8k16.row.col.f32.bf16.bf16.f32 "
        "{%0,%1,%2,%3}, {%4,%5,%6,%7}, {%8,%9}, {%0,%1,%2,%3};"
        : "+f"(c[0]),"+f"(c[1]),"+f"(c[2]),"+f"(c[3])
        : "r"(a[0]),"r"(a[1]),"r"(a[2]),"r"(a[3]), "r"(b[0]),"r"(b[1]));
}
__device__ __forceinline__ void ldm4(uint32_t* r, uint32_t addr){
    asm volatile("ldmatrix.sync.aligned.m8n8.x4.shared.b16 {%0,%1,%2,%3}, [%4];"
                 : "=r"(r[0]),"=r"(r[1]),"=r"(r[2]),"=r"(r[3]) : "r"(addr));
}

// ---------------- fp32 -> bf16 hi/lo split ----------------
__global__ void cvt_split(const float* __restrict__ src,
                          __nv_bfloat16* __restrict__ hi, __nv_bfloat16* __restrict__ lo)
{
    size_t i = ((size_t)blockIdx.x*256 + threadIdx.x)*4;
    float4 v = *(const float4*)(src + i);
    __nv_bfloat16 h0=__float2bfloat16(v.x), h1=__float2bfloat16(v.y);
    __nv_bfloat16 h2=__float2bfloat16(v.z), h3=__float2bfloat16(v.w);
    __nv_bfloat162 hp0; hp0.x=h0; hp0.y=h1;
    __nv_bfloat162 hp1; hp1.x=h2; hp1.y=h3;
    *(uint2*)(hi+i) = make_uint2(*(uint32_t*)&hp0, *(uint32_t*)&hp1);
    __nv_bfloat162 lp0, lp1;
    lp0.x=__float2bfloat16(v.x-__bfloat162float(h0)); lp0.y=__float2bfloat16(v.y-__bfloat162float(h1));
    lp1.x=__float2bfloat16(v.z-__bfloat162float(h2)); lp1.y=__float2bfloat16(v.w-__bfloat162float(h3));
    *(uint2*)(lo+i) = make_uint2(*(uint32_t*)&lp0, *(uint32_t*)&lp1);
}

// ---------------- multistage HMMA GEMM (bf16 hi/lo inputs, ldmatrix) ----------------
// C[M,N] = act(A @ W^T + b); CTA 128x128, BK=32, 3-stage cp.async pipeline.
#define BUFB 10240              /* 128 rows * 80B */
#define STGB (4*BUFB)           /* per-stage: Ah,Al,Wh,Wl */
#define NSTG 3
#define SMEMB (NSTG*STGB)

__device__ __forceinline__ void issue_stage(
    uint32_t sb, const __nv_bfloat16* Ah, const __nv_bfloat16* Al,
    const __nv_bfloat16* Wh, const __nv_bfloat16* Wl,
    int K, int m0, int n0, int k0, int t)
{
    #pragma unroll
    for (int i = 0; i < 2; i++){
        int q = t + i*256;
        int row = q >> 2, seg = q & 3;
        uint32_t so = row*80 + seg*16;
        size_t ga = (size_t)(m0+row)*K + k0 + seg*8;
        size_t gw = (size_t)(n0+row)*K + k0 + seg*8;
        cp16(sb + so,          Ah + ga);
        cp16(sb + BUFB + so,   Al + ga);
        cp16(sb + 2*BUFB + so, Wh + gw);
        cp16(sb + 3*BUFB + so, Wl + gw);
    }
}

__global__ __launch_bounds__(256) void tc_gemm(
    const __nv_bfloat16* __restrict__ Ah, const __nv_bfloat16* __restrict__ Al,
    const __nv_bfloat16* __restrict__ Wh, const __nv_bfloat16* __restrict__ Wl,
    const float* __restrict__ bias, float* __restrict__ C, int N, int K, int act)
{
    extern __shared__ char sm[];
    const uint32_t smb = smem_u32(sm);
    const int t = threadIdx.x, lane = t & 31, wid = t >> 5;
    const int m0 = blockIdx.y * 128, n0 = blockIdx.x * 128;
    const int wm = (wid & 3) * 32, wn = (wid >> 2) * 64;
    const int fr_ = lane >> 2, fc = (lane & 3) * 2;

    // per-lane ldmatrix base offsets (bytes)
    const int row_off = lane & 7, sel = lane >> 3;
    const uint32_t aoff = (uint32_t)(wm + (sel & 1)*8 + row_off)*80 + (uint32_t)(sel >> 1)*16;
    const uint32_t boff = (uint32_t)(wn + (sel >> 1)*8 + row_off)*80 + (uint32_t)(sel & 1)*16;

    float acc[2][8][4];
    #pragma unroll
    for (int i=0;i<2;i++)
        #pragma unroll
        for (int j=0;j<8;j++){ acc[i][j][0]=0.f; acc[i][j][1]=0.f; acc[i][j][2]=0.f; acc[i][j][3]=0.f; }

    const int niter = K >> 5;
    #pragma unroll
    for (int s = 0; s < NSTG-1; s++){
        issue_stage(smb + s*STGB, Ah, Al, Wh, Wl, K, m0, n0, s<<5, t);
        asm volatile("cp.async.commit_group;");
    }

    for (int it = 0; it < niter; it++){
        asm volatile("cp.async.wait_group 1;");
        __syncthreads();
        int nxt = it + NSTG - 1;
        if (nxt < niter)
            issue_stage(smb + (nxt%NSTG)*STGB, Ah, Al, Wh, Wl, K, m0, n0, nxt<<5, t);
        asm volatile("cp.async.commit_group;");

        const uint32_t stg = smb + (it%NSTG)*STGB;
        const uint32_t a_base = stg + aoff;
        const uint32_t b_base = stg + 2*BUFB + boff;

        #pragma unroll
        for (int ks = 0; ks < 2; ks++){
            const uint32_t ko = ks * 32;
            uint32_t ah[2][4], al[2][4];
            ldm4(ah[0], a_base + ko);
            ldm4(ah[1], a_base + 1280 + ko);
            ldm4(al[0], a_base + BUFB + ko);
            ldm4(al[1], a_base + BUFB + 1280 + ko);
            uint32_t bh[4][4], bl[4][4];
            #pragma unroll
            for (int p = 0; p < 4; p++){
                ldm4(bh[p], b_base + p*1280 + ko);
                ldm4(bl[p], b_base + BUFB + p*1280 + ko);
            }
            #pragma unroll
            for (int mi = 0; mi < 2; mi++)
                #pragma unroll
                for (int ni = 0; ni < 8; ni++){
                    const uint32_t* bhp = &bh[ni>>1][(ni&1)*2];
                    const uint32_t* blp = &bl[ni>>1][(ni&1)*2];
                    mma16816(acc[mi][ni], ah[mi], bhp);
                    mma16816(acc[mi][ni], ah[mi], blp);
                    mma16816(acc[mi][ni], al[mi], bhp);
                }
        }
        __syncthreads();
    }

    #pragma unroll
    for (int mi = 0; mi < 2; mi++){
        #pragma unroll
        for (int ni = 0; ni < 8; ni++){
            int m = m0 + wm + mi * 16 + fr_;
            int n = n0 + wn + ni * 8 + fc;
            float b0 = bias[n], b1 = bias[n + 1];
            float v0 = acc[mi][ni][0] + b0, v1 = acc[mi][ni][1] + b1;
            float v2 = acc[mi][ni][2] + b0, v3 = acc[mi][ni][3] + b1;
            if (act){ v0 = gelu_f(v0); v1 = gelu_f(v1); v2 = gelu_f(v2); v3 = gelu_f(v3); }
            *(float2*)&C[(size_t)m * N + n]       = make_float2(v0, v1);
            *(float2*)&C[(size_t)(m + 8) * N + n] = make_float2(v2, v3);
        }
    }
}

// ---------------- per-(b,c) mean/rstd over HW (fp32) ----------------
__global__ void stats_kernel(const float* __restrict__ A, float* __restrict__ mean,
                             float* __restrict__ rstd, int C)
{
    const int b = blockIdx.y, c = blockIdx.x*32 + threadIdx.x, ty = threadIdx.y;
    const float* base = A + (size_t)b*HWd*C + c;
    float s=0.f, s2=0.f;
    for (int hw=ty; hw<HWd; hw+=16){ float v = base[(size_t)hw*C]; s+=v; s2+=v*v; }
    __shared__ float ss[16][33], sq[16][33];
    ss[ty][threadIdx.x]=s; sq[ty][threadIdx.x]=s2;
    __syncthreads();
    if (ty==0){
        #pragma unroll
        for (int i=1;i<16;i++){ s+=ss[i][threadIdx.x]; s2+=sq[i][threadIdx.x]; }
        float m = s*(1.f/HWd), var = s2*(1.f/HWd) - m*m;
        mean[b*C+c]=m; rstd[b*C+c]=rsqrtf(var + 1e-5f);
    }
}

// ---------------- lang 1x1 conv: mode 1 gelu, 2 mask, 4 transpose, 8 inorm(NL) ----
__global__ __launch_bounds__(256) void lang_conv_kernel(
    const float* __restrict__ in, const float* __restrict__ w,
    const float* __restrict__ bias, const float* __restrict__ mask,
    float* __restrict__ out, int Cout, int mode)
{
    __shared__ float in_s[32][33];
    __shared__ float w_s [32][33];
    const int b = blockIdx.x, o0 = blockIdx.y*32, t = threadIdx.x;
    const int n = t & 31, og = t >> 5;
    float acc[4] = {0.f,0.f,0.f,0.f};
    for (int i0 = 0; i0 < CLd; i0 += 32){
        for (int e = t; e < 1024; e += 256) in_s[e>>5][e&31] = in[((size_t)b*CLd + i0+(e>>5))*NLd + (e&31)];
        for (int e = t; e < 1024; e += 256) w_s[e>>5][e&31]  = w[(size_t)(o0+(e>>5))*CLd + i0+(e&31)];
        __syncthreads();
        #pragma unroll
        for (int ii = 0; ii < 32; ii++){
            float iv = in_s[ii][n];
            acc[0]+=w_s[og   ][ii]*iv; acc[1]+=w_s[og+ 8][ii]*iv;
            acc[2]+=w_s[og+16][ii]*iv; acc[3]+=w_s[og+24][ii]*iv;
        }
        __syncthreads();
    }
    float mv = (mode & 2) ? mask[b*NLd + n] : 1.f;
    #pragma unroll
    for (int j = 0; j < 4; j++){
        int o = o0 + og + 8*j;
        float v = acc[j] + bias[o];
        if (mode & 2) v *= mv;
        if (mode & 8){
            float s=v, s2=v*v;
            #pragma unroll
            for (int off=16;off;off>>=1){ s+=__shfl_xor_sync(~0u,s,off); s2+=__shfl_xor_sync(~0u,s2,off); }
            float mn = s*(1.f/32.f), vr = s2*(1.f/32.f) - mn*mn;
            v = (v-mn)*rsqrtf(vr + 1e-5f);
        }
        if (mode & 1) v = gelu_f(v);
        if (mode & 4) out[((size_t)b*NLd + n)*Cout + o] = v;
        else          out[((size_t)b*Cout + o)*NLd + n] = v;
    }
}

// ---------------- sim = inorm(q).k * scale + 1e4*mask - 1e4 ----------------
__global__ __launch_bounds__(256) void sim_kernel(const float* __restrict__ mask)
{
    __shared__ float ks[64*32];
    __shared__ float qm[64], qr[64], mk[32];
    __shared__ float qrow[8][64];
    const int bh = blockIdx.y, b = bh>>3, h = bh&7;
    const int t = threadIdx.x, w = t>>5, lane = t&31;
    for (int e = t; e < 2048; e += 256) ks[e] = g_k[((size_t)b*Kch + h*64)*NLd + e];
    if (t < 64){ qm[t]=g_mq[b*Kch+h*64+t]; qr[t]=g_rq[b*Kch+h*64+t]; }
    if (t >= 64 && t < 96) mk[t-64]=mask[b*NLd+t-64];
    __syncthreads();
    const int hw0 = blockIdx.x*1024;
    for (int it = 0; it < 128; it++){
        int hw = hw0 + it*8 + w;
        const float2 q2 = ((const float2*)&g_q[((size_t)(b*HWd+hw))*Kch + h*64])[lane];
        qrow[w][2*lane  ] = (q2.x - qm[2*lane  ])*qr[2*lane  ];
        qrow[w][2*lane+1] = (q2.y - qm[2*lane+1])*qr[2*lane+1];
        __syncwarp();
        float acc = 0.f;
        #pragma unroll 16
        for (int d = 0; d < 64; d++) acc += qrow[w][d]*ks[d*32+lane];
        g_sim[((size_t)bh*HWd+hw)*32+lane] =
            acc*0.044194173824159216f + 10000.f*mk[lane] - 10000.f;
        __syncwarp();
    }
}

// ---------------- lang->image softmax stats over HW ----------------
__global__ void latt_stats_kernel()
{
    const int bh = blockIdx.x, n = threadIdx.x, ty = threadIdx.y;
    float m = -1e30f, s = 0.f;
    for (int hw = ty; hw < HWd; hw += 32){
        float v = g_sim[((size_t)bh*HWd+hw)*32 + n];
        float nm = fmaxf(m, v);
        s = s*__expf(m-nm) + __expf(v-nm); m = nm;
    }
    __shared__ float sm_[32][33], ss[32][33];
    sm_[ty][n]=m; ss[ty][n]=s;
    __syncthreads();
    if (ty == 0){
        for (int i = 1; i < 32; i++){
            float m2=sm_[i][n], s2=ss[i][n], nm=fmaxf(m,m2);
            s = s*__expf(m-nm) + s2*__expf(m2-nm); m = nm;
        }
        g_lmax[bh*32+n]=m; g_lsum[bh*32+n]=s;
    }
}

// ---------------- image->lang: att_out = softmax_n(sim) . v  (bf16 hi/lo out) ----
__global__ __launch_bounds__(256) void attout_kernel()
{
    __shared__ float v_s[32*68];
    const int bh=blockIdx.y, b=bh>>3, h=bh&7, t=threadIdx.x;
    for (int e=t;e<2048;e+=256) v_s[(e&31)*68+(e>>5)] = g_v[((size_t)b*Vch + h*64)*NLd + e];
    __syncthreads();
    const int hw = blockIdx.x*256 + t;
    const float4* sp = (const float4*)&g_sim[((size_t)bh*HWd+hw)*32];
    float sv[32];
    #pragma unroll
    for (int j=0;j<8;j++){ float4 s4=sp[j]; sv[4*j]=s4.x; sv[4*j+1]=s4.y; sv[4*j+2]=s4.z; sv[4*j+3]=s4.w; }
    float mx=-1e30f;
    #pragma unroll
    for (int i=0;i<32;i++) mx=fmaxf(mx,sv[i]);
    float sum=0.f;
    #pragma unroll
    for (int i=0;i<32;i++){ sv[i]=__expf(sv[i]-mx); sum+=sv[i]; }
    float inv=1.f/sum;
    float acc[64];
    #pragma unroll
    for (int i=0;i<64;i++) acc[i]=0.f;
    #pragma unroll 4
    for (int n=0;n<32;n++){
        float a = sv[n]*inv;
        const float4* vr = (const float4*)&v_s[n*68];
        #pragma unroll
        for (int j=0;j<16;j++){
            float4 vv = vr[j];
            acc[4*j]+=a*vv.x; acc[4*j+1]+=a*vv.y; acc[4*j+2]+=a*vv.z; acc[4*j+3]+=a*vv.w;
        }
    }
    size_t base = (size_t)(b*HWd+hw)*Vch + h*64;
    #pragma unroll
    for (int j=0;j<16;j++){
        __nv_bfloat162 hp, lp;
        float a0=acc[4*j], a1=acc[4*j+1], a2=acc[4*j+2], a3=acc[4*j+3];
        hp.x=__float2bfloat16(a0); hp.y=__float2bfloat16(a1);
        lp.x=__float2bfloat16(a0-__bfloat162float(hp.x)); lp.y=__float2bfloat16(a1-__bfloat162float(hp.y));
        __nv_bfloat162 hq, lq;
        hq.x=__float2bfloat16(a2); hq.y=__float2bfloat16(a3);
        lq.x=__float2bfloat16(a2-__bfloat162float(hq.x)); lq.y=__float2bfloat16(a3-__bfloat162float(hq.y));
        *(uint2*)(g_ath+base+4*j) = make_uint2(*(uint32_t*)&hp, *(uint32_t*)&hq);
        *(uint2*)(g_atl+base+4*j) = make_uint2(*(uint32_t*)&lp, *(uint32_t*)&lq);
    }
}

// ---------------- lang_out partials: latt . inorm(lv) over an HW slice ----------
__global__ __launch_bounds__(256) void langout_part_kernel()
{
    __shared__ float ps[32*32];
    __shared__ float lvs[32*96];
    __shared__ float lmx[32], lsm[32];
    const int bh=blockIdx.x, spl=blockIdx.y, b=bh>>3, h=bh&7, t=threadIdx.x;
    if (t<32){ lmx[t]=g_lmax[bh*32+t]; lsm[t]=1.f/g_lsum[bh*32+t]; }
    __syncthreads();
    const int n=t&31, c0=(t>>5)*12;
    float acc[12];
    #pragma unroll
    for (int j=0;j<12;j++) acc[j]=0.f;
    const int hwA = spl*(HWd/SPL), hwB = hwA + HWd/SPL;
    for (int hw0=hwA; hw0<hwB; hw0+=32){
        for (int e=t;e<1024;e+=256){
            int r=e>>5, nn=e&31;
            ps[e]=__expf(g_sim[((size_t)bh*HWd+hw0+r)*32+nn]-lmx[nn])*lsm[nn];
        }
        for (int e=t;e<3072;e+=256){
            int r=e/96, cc=e-r*96, ch=h*96+cc;
            lvs[e]=(g_lv[((size_t)(b*HWd+hw0+r))*CLd+ch]-g_mlv[b*CLd+ch])*g_rlv[b*CLd+ch];
        }
        __syncthreads();
        #pragma unroll 8
        for (int r=0;r<32;r++){
            float p=ps[r*32+n];
            #pragma unroll
            for (int j=0;j<12;j++) acc[j]+=p*lvs[r*96+c0+j];
        }
        __syncthreads();
    }
    #pragma unroll
    for (int j=0;j<12;j++)
        g_lop[spl][((size_t)b*CLd + h*96+c0+j)*NLd + n] = acc[j];
}

// ---------------- reduce partials + mask -> g_lo1 ----------------
__global__ void lo1_reduce_kernel(const float* __restrict__ mask)
{
    const int idx = blockIdx.x*256 + threadIdx.x;
    float s = 0.f;
    #pragma unroll
    for (int p = 0; p < SPL; p++) s += g_lop[p][idx];
    int n = idx & 31, b = idx / (CLd*NLd);
    g_lo1[idx] = s * mask[b*NLd + n];
}

// ---------------- z = vis * inorm(vo)  ->  bf16 hi/lo ----------------
__global__ void zmul_kernel()
{
    size_t i = ((size_t)blockIdx.x*256 + threadIdx.x)*4;
    int c = (int)(i & 511);
    int b = (int)((i >> 9) >> 12);
    float4 vi = *(const float4*)&g_vis[i];
    float4 vo = *(const float4*)&g_vo[i];
    float z0 = vi.x*(vo.x-g_mw[b*Vch+c  ])*g_rw[b*Vch+c  ];
    float z1 = vi.y*(vo.y-g_mw[b*Vch+c+1])*g_rw[b*Vch+c+1];
    float z2 = vi.z*(vo.z-g_mw[b*Vch+c+2])*g_rw[b*Vch+c+2];
    float z3 = vi.w*(vo.w-g_mw[b*Vch+c+3])*g_rw[b*Vch+c+3];
    __nv_bfloat162 hp, hq, lp, lq;
    hp.x=__float2bfloat16(z0); hp.y=__float2bfloat16(z1);
    hq.x=__float2bfloat16(z2); hq.y=__float2bfloat16(z3);
    lp.x=__float2bfloat16(z0-__bfloat162float(hp.x)); lp.y=__float2bfloat16(z1-__bfloat162float(hp.y));
    lq.x=__float2bfloat16(z2-__bfloat162float(hq.x)); lq.y=__float2bfloat16(z3-__bfloat162float(hq.y));
    *(uint2*)(g_zh+i) = make_uint2(*(uint32_t*)&hp, *(uint32_t*)&hq);
    *(uint2*)(g_zl+i) = make_uint2(*(uint32_t*)&lp, *(uint32_t*)&lq);
}

// ---------------- elementwise: zt = lang * lang_out2 ----------------
__global__ void ztmul_kernel()
{
    size_t i = ((size_t)blockIdx.x*256 + threadIdx.x)*4;
    float4 a = *(const float4*)&g_lang[i];
    float4 b4 = *(const float4*)&g_lo2[i];
    float4 r; r.x=a.x*b4.x; r.y=a.y*b4.y; r.z=a.z*b4.z; r.w=a.w*b4.w;
    *(float4*)&g_zt[i] = r;
}

extern "C" void kernel_launch(void* const* d_in, const int* in_sizes, int n_in,
                              void* d_out, int out_size)
{
    const float* x      = (const float*)d_in[0];
    const float* l      = (const float*)d_in[1];
    const float* lmask  = (const float*)d_in[2];
    const float* w_vis  = (const float*)d_in[3];  const float* b_vis  = (const float*)d_in[4];
    const float* w_langp= (const float*)d_in[5];  const float* b_langp= (const float*)d_in[6];
    const float* w_q    = (const float*)d_in[7];  const float* b_q    = (const float*)d_in[8];
    const float* w_k    = (const float*)d_in[9];  const float* b_k    = (const float*)d_in[10];
    const float* w_v    = (const float*)d_in[11]; const float* b_v    = (const float*)d_in[12];
    const float* w_lv   = (const float*)d_in[13]; const float* b_lv   = (const float*)d_in[14];
    const float* w_W    = (const float*)d_in[15]; const float* b_W    = (const float*)d_in[16];
    const float* w_langW= (const float*)d_in[17]; const float* b_langW= (const float*)d_in[18];
    const float* w_mm   = (const float*)d_in[19]; const float* b_mm   = (const float*)d_in[20];
    const float* w_langmm=(const float*)d_in[21]; const float* b_langmm=(const float*)d_in[22];
    float* out = (float*)d_out;

    float *p_vis, *p_q, *p_lv, *p_vo, *p_lang, *p_k, *p_v, *p_lo1, *p_lo2, *p_zt;
    float *p_mq, *p_rq, *p_mlv, *p_rlv, *p_mw, *p_rw;
    __nv_bfloat16 *p_xh, *p_xl, *p_ath, *p_atl, *p_zh, *p_zl, *p_wh, *p_wl;
    cudaGetSymbolAddress((void**)&p_vis, g_vis);  cudaGetSymbolAddress((void**)&p_q,  g_q);
    cudaGetSymbolAddress((void**)&p_lv,  g_lv);   cudaGetSymbolAddress((void**)&p_vo, g_vo);
    cudaGetSymbolAddress((void**)&p_lang,g_lang); cudaGetSymbolAddress((void**)&p_k,  g_k);
    cudaGetSymbolAddress((void**)&p_v,   g_v);    cudaGetSymbolAddress((void**)&p_lo1,g_lo1);
    cudaGetSymbolAddress((void**)&p_lo2, g_lo2);  cudaGetSymbolAddress((void**)&p_zt, g_zt);
    cudaGetSymbolAddress((void**)&p_mq,  g_mq);   cudaGetSymbolAddress((void**)&p_rq, g_rq);
    cudaGetSymbolAddress((void**)&p_mlv, g_mlv);  cudaGetSymbolAddress((void**)&p_rlv,g_rlv);
    cudaGetSymbolAddress((void**)&p_mw,  g_mw);   cudaGetSymbolAddress((void**)&p_rw, g_rw);
    cudaGetSymbolAddress((void**)&p_xh,  g_xh);   cudaGetSymbolAddress((void**)&p_xl, g_xl);
    cudaGetSymbolAddress((void**)&p_ath, g_ath);  cudaGetSymbolAddress((void**)&p_atl,g_atl);
    cudaGetSymbolAddress((void**)&p_zh,  g_zh);   cudaGetSymbolAddress((void**)&p_zl, g_zl);
    cudaGetSymbolAddress((void**)&p_wh,  g_wh);   cudaGetSymbolAddress((void**)&p_wl, g_wl);

    cudaFuncSetAttribute(tc_gemm, cudaFuncAttributeMaxDynamicSharedMemorySize, SMEMB);

    dim3 blk256(256);
    // pre-convert x + weights to bf16 hi/lo
    cvt_split<<<(int)(((size_t)Mm*Dd)/1024), blk256>>>(x, p_xh, p_xl);
    cvt_split<<<262144/1024, blk256>>>(w_vis, p_wh+WOFF_VIS, p_wl+WOFF_VIS);
    cvt_split<<<262144/1024, blk256>>>(w_q,   p_wh+WOFF_Q,   p_wl+WOFF_Q);
    cvt_split<<<393216/1024, blk256>>>(w_lv,  p_wh+WOFF_LV,  p_wl+WOFF_LV);
    cvt_split<<<262144/1024, blk256>>>(w_W,   p_wh+WOFF_W,   p_wl+WOFF_W);
    cvt_split<<<262144/1024, blk256>>>(w_mm,  p_wh+WOFF_MM,  p_wl+WOFF_MM);
    // big GEMMs
    tc_gemm<<<dim3(Dd/128,  Mm/128), blk256, SMEMB>>>(p_xh, p_xl, p_wh+WOFF_VIS, p_wl+WOFF_VIS, b_vis, p_vis, Dd,  Dd, 1);
    tc_gemm<<<dim3(Kch/128, Mm/128), blk256, SMEMB>>>(p_xh, p_xl, p_wh+WOFF_Q,   p_wl+WOFF_Q,   b_q,   p_q,   Kch, Dd, 0);
    tc_gemm<<<dim3(CLd/128, Mm/128), blk256, SMEMB>>>(p_xh, p_xl, p_wh+WOFF_LV,  p_wl+WOFF_LV,  b_lv,  p_lv,  CLd, Dd, 0);
    stats_kernel<<<dim3(Kch/32, Bb), dim3(32,16)>>>(p_q,  p_mq,  p_rq,  Kch);
    stats_kernel<<<dim3(CLd/32, Bb), dim3(32,16)>>>(p_lv, p_mlv, p_rlv, CLd);
    // lang-side convs
    lang_conv_kernel<<<dim3(Bb, CLd/32), blk256>>>(l, w_langp, b_langp, lmask, p_lang, CLd, 1);
    lang_conv_kernel<<<dim3(Bb, Kch/32), blk256>>>(l, w_k, b_k, lmask, p_k, Kch, 2);
    lang_conv_kernel<<<dim3(Bb, Vch/32), blk256>>>(l, w_v, b_v, lmask, p_v, Vch, 2);
    // attention
    sim_kernel<<<dim3(HWd/1024, Bb*Hh), blk256>>>(lmask);
    latt_stats_kernel<<<Bb*Hh, dim3(32,32)>>>();
    attout_kernel<<<dim3(HWd/256, Bb*Hh), blk256>>>();
    langout_part_kernel<<<dim3(Bb*Hh, SPL), blk256>>>();
    lo1_reduce_kernel<<<(Bb*CLd*NLd)/256, blk256>>>(lmask);
    // lang_out2 = inorm(conv(lang_out, w_langW))
    lang_conv_kernel<<<dim3(Bb, CLd/32), blk256>>>(p_lo1, w_langW, b_langW, lmask, p_lo2, CLd, 8);
    // vis_out = inorm(conv(att_out, w_W))
    tc_gemm<<<dim3(Vch/128, Mm/128), blk256, SMEMB>>>(p_ath, p_atl, p_wh+WOFF_W, p_wl+WOFF_W, b_W, p_vo, Vch, Vch, 0);
    stats_kernel<<<dim3(Vch/32, Bb), dim3(32,16)>>>(p_vo, p_mw, p_rw, Vch);
    zmul_kernel<<<(int)(((size_t)Mm*Vch)/1024), blk256>>>();
    // mm = gelu(conv(z, w_mm)) -> out[0 : M*V]
    tc_gemm<<<dim3(Vch/128, Mm/128), blk256, SMEMB>>>(p_zh, p_zl, p_wh+WOFF_MM, p_wl+WOFF_MM, b_mm, out, Vch, Vch, 1);
    // lang_mm = gelu(conv(lang*lo2, w_langmm)) transposed -> out tail
    ztmul_kernel<<<(Bb*CLd*NLd)/1024, blk256>>>();
    lang_conv_kernel<<<dim3(Bb, CLd/32), blk256>>>(p_zt, w_langmm, b_langmm, lmask,
                                                   out + (size_t)Mm*Vch, CLd, 1|4);
    (void)in_sizes; (void)n_in; (void)out_size;
}

// round 13
// speedup vs baseline: 1.6099x; 1.6099x over previous
#include <cuda_runtime.h>
#include <cuda_bf16.h>
#include <math.h>
#include <stdint.h>

#define Bb   16
#define HWd  4096
#define Dd   512
#define CLd  768
#define Kch  512
#define Vch  512
#define NLd  32
#define Hh   8
#define Mm   (Bb*HWd)
#define SPL  8

// ---------------- scratch ----------------
static __device__ float g_vis[(size_t)Mm*Dd];
static __device__ float g_q  [(size_t)Mm*Kch];
static __device__ float g_lv [(size_t)Mm*CLd];
static __device__ float g_vo [(size_t)Mm*Vch];
static __device__ float g_sim[(size_t)Bb*Hh*HWd*NLd];
static __device__ __nv_bfloat16 g_xh[(size_t)Mm*Dd],  g_xl[(size_t)Mm*Dd];
static __device__ __nv_bfloat16 g_ath[(size_t)Mm*Vch], g_atl[(size_t)Mm*Vch];
static __device__ __nv_bfloat16 g_zh[(size_t)Mm*Vch],  g_zl[(size_t)Mm*Vch];
#define WOFF_VIS 0
#define WOFF_Q   262144
#define WOFF_LV  524288
#define WOFF_W   917504
#define WOFF_MM  1179648
static __device__ __nv_bfloat16 g_wh[1441792], g_wl[1441792];
static __device__ float g_lang[Bb*CLd*NLd];
static __device__ float g_k  [Bb*Kch*NLd];
static __device__ float g_v  [Bb*Vch*NLd];
static __device__ float g_lop[SPL][Bb*CLd*NLd];
static __device__ float g_lo1[Bb*CLd*NLd];
static __device__ float g_lo2[Bb*CLd*NLd];
static __device__ float g_zt [Bb*CLd*NLd];
static __device__ float g_mq [Bb*Kch],  g_rq [Bb*Kch];
static __device__ float g_mlv[Bb*CLd],  g_rlv[Bb*CLd];
static __device__ float g_mw [Bb*Vch],  g_rw [Bb*Vch];
static __device__ float g_lmax[Bb*Hh*NLd], g_lsum[Bb*Hh*NLd];

__device__ __forceinline__ float gelu_f(float x){
    return 0.5f*x*(1.0f + erff(x*0.70710678118654752f));
}
__device__ __forceinline__ uint32_t smem_u32(const void* p){
    uint32_t a;
    asm("{ .reg .u64 t; cvta.to.shared.u64 t, %1; cvt.u32.u64 %0, t; }" : "=r"(a) : "l"(p));
    return a;
}
__device__ __forceinline__ void cp16(uint32_t s, const void* g){
    asm volatile("cp.async.cg.shared.global [%0], [%1], 16;" :: "r"(s), "l"(g));
}
__device__ __forceinline__ void mma16816(float* c, const uint32_t* a, const uint32_t* b){
    asm volatile("mma.sync.aligned.m16n8k16.row.col.f32.bf16.bf16.f32 "
        "{%0,%1,%2,%3}, {%4,%5,%6,%7}, {%8,%9}, {%0,%1,%2,%3};"
        : "+f"(c[0]),"+f"(c[1]),"+f"(c[2]),"+f"(c[3])
        : "r"(a[0]),"r"(a[1]),"r"(a[2]),"r"(a[3]), "r"(b[0]),"r"(b[1]));
}

// ---------------- fp32 -> bf16 hi/lo split ----------------
__global__ void cvt_split(const float* __restrict__ src,
                          __nv_bfloat16* __restrict__ hi, __nv_bfloat16* __restrict__ lo)
{
    size_t i = ((size_t)blockIdx.x*256 + threadIdx.x)*4;
    float4 v = *(const float4*)(src + i);
    __nv_bfloat16 h0=__float2bfloat16(v.x), h1=__float2bfloat16(v.y);
    __nv_bfloat16 h2=__float2bfloat16(v.z), h3=__float2bfloat16(v.w);
    __nv_bfloat162 hp0; hp0.x=h0; hp0.y=h1;
    __nv_bfloat162 hp1; hp1.x=h2; hp1.y=h3;
    *(uint2*)(hi+i) = make_uint2(*(uint32_t*)&hp0, *(uint32_t*)&hp1);
    __nv_bfloat162 lp0, lp1;
    lp0.x=__float2bfloat16(v.x-__bfloat162float(h0)); lp0.y=__float2bfloat16(v.y-__bfloat162float(h1));
    lp1.x=__float2bfloat16(v.z-__bfloat162float(h2)); lp1.y=__float2bfloat16(v.w-__bfloat162float(h3));
    *(uint2*)(lo+i) = make_uint2(*(uint32_t*)&lp0, *(uint32_t*)&lp1);
}

// ---------------- multistage HMMA GEMM (bf16 hi/lo, scalar frag loads) ----------------
// C[M,N] = act(A @ W^T + b); CTA 128x128, BK=32, 2-stage cp.async double buffer.
// 2 stages * 40KB = 80KB smem -> 2 CTAs/SM (4 warps/SMSP) for latency hiding.
#define BUFB 10240              /* 128 rows * 80B */
#define STGB (4*BUFB)           /* per-stage: Ah,Al,Wh,Wl */
#define NSTG 2
#define SMEMB (NSTG*STGB)

__device__ __forceinline__ void issue_stage(
    uint32_t sb, const __nv_bfloat16* Ah, const __nv_bfloat16* Al,
    const __nv_bfloat16* Wh, const __nv_bfloat16* Wl,
    int K, int m0, int n0, int k0, int t)
{
    #pragma unroll
    for (int i = 0; i < 2; i++){
        int q = t + i*256;
        int row = q >> 2, seg = q & 3;
        uint32_t so = row*80 + seg*16;
        size_t ga = (size_t)(m0+row)*K + k0 + seg*8;
        size_t gw = (size_t)(n0+row)*K + k0 + seg*8;
        cp16(sb + so,          Ah + ga);
        cp16(sb + BUFB + so,   Al + ga);
        cp16(sb + 2*BUFB + so, Wh + gw);
        cp16(sb + 3*BUFB + so, Wl + gw);
    }
}

__global__ __launch_bounds__(256) void tc_gemm(
    const __nv_bfloat16* __restrict__ Ah, const __nv_bfloat16* __restrict__ Al,
    const __nv_bfloat16* __restrict__ Wh, const __nv_bfloat16* __restrict__ Wl,
    const float* __restrict__ bias, float* __restrict__ C, int N, int K, int act)
{
    extern __shared__ char sm[];
    const uint32_t smb = smem_u32(sm);
    const int t = threadIdx.x, lane = t & 31, wid = t >> 5;
    const int m0 = blockIdx.y * 128, n0 = blockIdx.x * 128;
    const int wm = (wid & 3) * 32, wn = (wid >> 2) * 64;
    const int fr_ = lane >> 2, fc = (lane & 3) * 2;

    float acc[2][8][4];
    #pragma unroll
    for (int i=0;i<2;i++)
        #pragma unroll
        for (int j=0;j<8;j++){ acc[i][j][0]=0.f; acc[i][j][1]=0.f; acc[i][j][2]=0.f; acc[i][j][3]=0.f; }

    const int niter = K >> 5;
    issue_stage(smb, Ah, Al, Wh, Wl, K, m0, n0, 0, t);
    asm volatile("cp.async.commit_group;");

    for (int it = 0; it < niter; it++){
        if (it + 1 < niter){
            issue_stage(smb + ((it+1)&1)*STGB, Ah, Al, Wh, Wl, K, m0, n0, (it+1)<<5, t);
            asm volatile("cp.async.commit_group;");
            asm volatile("cp.async.wait_group 1;");
        } else {
            asm volatile("cp.async.wait_group 0;");
        }
        __syncthreads();

        const char* sb = sm + (it&1)*STGB;
        const char* sa_h = sb;
        const char* sa_l = sb + BUFB;
        const char* sw_h = sb + 2*BUFB;
        const char* sw_l = sb + 3*BUFB;

        #pragma unroll
        for (int ks = 0; ks < 2; ks++){
            const int kk = ks * 16;
            uint32_t ah[2][4], al[2][4];
            #pragma unroll
            for (int mi = 0; mi < 2; mi++){
                int r = wm + mi * 16 + fr_;
                ah[mi][0] = *(const uint32_t*)(sa_h + (r    )*80 + (kk+fc)*2);
                ah[mi][1] = *(const uint32_t*)(sa_h + (r + 8)*80 + (kk+fc)*2);
                ah[mi][2] = *(const uint32_t*)(sa_h + (r    )*80 + (kk+fc+8)*2);
                ah[mi][3] = *(const uint32_t*)(sa_h + (r + 8)*80 + (kk+fc+8)*2);
                al[mi][0] = *(const uint32_t*)(sa_l + (r    )*80 + (kk+fc)*2);
                al[mi][1] = *(const uint32_t*)(sa_l + (r + 8)*80 + (kk+fc)*2);
                al[mi][2] = *(const uint32_t*)(sa_l + (r    )*80 + (kk+fc+8)*2);
                al[mi][3] = *(const uint32_t*)(sa_l + (r + 8)*80 + (kk+fc+8)*2);
            }
            uint32_t bh[8][2], bl[8][2];
            #pragma unroll
            for (int ni = 0; ni < 8; ni++){
                int n = wn + ni * 8 + fr_;
                bh[ni][0] = *(const uint32_t*)(sw_h + n*80 + (kk+fc)*2);
                bh[ni][1] = *(const uint32_t*)(sw_h + n*80 + (kk+fc+8)*2);
                bl[ni][0] = *(const uint32_t*)(sw_l + n*80 + (kk+fc)*2);
                bl[ni][1] = *(const uint32_t*)(sw_l + n*80 + (kk+fc+8)*2);
            }
            #pragma unroll
            for (int mi = 0; mi < 2; mi++)
                #pragma unroll
                for (int ni = 0; ni < 8; ni++){
                    mma16816(acc[mi][ni], ah[mi], bh[ni]);
                    mma16816(acc[mi][ni], ah[mi], bl[ni]);
                    mma16816(acc[mi][ni], al[mi], bh[ni]);
                }
        }
        __syncthreads();
    }

    #pragma unroll
    for (int mi = 0; mi < 2; mi++){
        #pragma unroll
        for (int ni = 0; ni < 8; ni++){
            int m = m0 + wm + mi * 16 + fr_;
            int n = n0 + wn + ni * 8 + fc;
            float b0 = bias[n], b1 = bias[n + 1];
            float v0 = acc[mi][ni][0] + b0, v1 = acc[mi][ni][1] + b1;
            float v2 = acc[mi][ni][2] + b0, v3 = acc[mi][ni][3] + b1;
            if (act){ v0 = gelu_f(v0); v1 = gelu_f(v1); v2 = gelu_f(v2); v3 = gelu_f(v3); }
            *(float2*)&C[(size_t)m * N + n]       = make_float2(v0, v1);
            *(float2*)&C[(size_t)(m + 8) * N + n] = make_float2(v2, v3);
        }
    }
}

// ---------------- per-(b,c) mean/rstd over HW (fp32) ----------------
__global__ void stats_kernel(const float* __restrict__ A, float* __restrict__ mean,
                             float* __restrict__ rstd, int C)
{
    const int b = blockIdx.y, c = blockIdx.x*32 + threadIdx.x, ty = threadIdx.y;
    const float* base = A + (size_t)b*HWd*C + c;
    float s=0.f, s2=0.f;
    for (int hw=ty; hw<HWd; hw+=16){ float v = base[(size_t)hw*C]; s+=v; s2+=v*v; }
    __shared__ float ss[16][33], sq[16][33];
    ss[ty][threadIdx.x]=s; sq[ty][threadIdx.x]=s2;
    __syncthreads();
    if (ty==0){
        #pragma unroll
        for (int i=1;i<16;i++){ s+=ss[i][threadIdx.x]; s2+=sq[i][threadIdx.x]; }
        float m = s*(1.f/HWd), var = s2*(1.f/HWd) - m*m;
        mean[b*C+c]=m; rstd[b*C+c]=rsqrtf(var + 1e-5f);
    }
}

// ---------------- lang 1x1 conv: mode 1 gelu, 2 mask, 4 transpose, 8 inorm(NL) ----
__global__ __launch_bounds__(256) void lang_conv_kernel(
    const float* __restrict__ in, const float* __restrict__ w,
    const float* __restrict__ bias, const float* __restrict__ mask,
    float* __restrict__ out, int Cout, int mode)
{
    __shared__ float in_s[32][33];
    __shared__ float w_s [32][33];
    const int b = blockIdx.x, o0 = blockIdx.y*32, t = threadIdx.x;
    const int n = t & 31, og = t >> 5;
    float acc[4] = {0.f,0.f,0.f,0.f};
    for (int i0 = 0; i0 < CLd; i0 += 32){
        for (int e = t; e < 1024; e += 256) in_s[e>>5][e&31] = in[((size_t)b*CLd + i0+(e>>5))*NLd + (e&31)];
        for (int e = t; e < 1024; e += 256) w_s[e>>5][e&31]  = w[(size_t)(o0+(e>>5))*CLd + i0+(e&31)];
        __syncthreads();
        #pragma unroll
        for (int ii = 0; ii < 32; ii++){
            float iv = in_s[ii][n];
            acc[0]+=w_s[og   ][ii]*iv; acc[1]+=w_s[og+ 8][ii]*iv;
            acc[2]+=w_s[og+16][ii]*iv; acc[3]+=w_s[og+24][ii]*iv;
        }
        __syncthreads();
    }
    float mv = (mode & 2) ? mask[b*NLd + n] : 1.f;
    #pragma unroll
    for (int j = 0; j < 4; j++){
        int o = o0 + og + 8*j;
        float v = acc[j] + bias[o];
        if (mode & 2) v *= mv;
        if (mode & 8){
            float s=v, s2=v*v;
            #pragma unroll
            for (int off=16;off;off>>=1){ s+=__shfl_xor_sync(~0u,s,off); s2+=__shfl_xor_sync(~0u,s2,off); }
            float mn = s*(1.f/32.f), vr = s2*(1.f/32.f) - mn*mn;
            v = (v-mn)*rsqrtf(vr + 1e-5f);
        }
        if (mode & 1) v = gelu_f(v);
        if (mode & 4) out[((size_t)b*NLd + n)*Cout + o] = v;
        else          out[((size_t)b*Cout + o)*NLd + n] = v;
    }
}

// ---------------- sim = inorm(q).k * scale + 1e4*mask - 1e4 ----------------
__global__ __launch_bounds__(256) void sim_kernel(const float* __restrict__ mask)
{
    __shared__ float ks[64*32];
    __shared__ float qm[64], qr[64], mk[32];
    __shared__ float qrow[8][64];
    const int bh = blockIdx.y, b = bh>>3, h = bh&7;
    const int t = threadIdx.x, w = t>>5, lane = t&31;
    for (int e = t; e < 2048; e += 256) ks[e] = g_k[((size_t)b*Kch + h*64)*NLd + e];
    if (t < 64){ qm[t]=g_mq[b*Kch+h*64+t]; qr[t]=g_rq[b*Kch+h*64+t]; }
    if (t >= 64 && t < 96) mk[t-64]=mask[b*NLd+t-64];
    __syncthreads();
    const int hw0 = blockIdx.x*1024;
    for (int it = 0; it < 128; it++){
        int hw = hw0 + it*8 + w;
        const float2 q2 = ((const float2*)&g_q[((size_t)(b*HWd+hw))*Kch + h*64])[lane];
        qrow[w][2*lane  ] = (q2.x - qm[2*lane  ])*qr[2*lane  ];
        qrow[w][2*lane+1] = (q2.y - qm[2*lane+1])*qr[2*lane+1];
        __syncwarp();
        float acc = 0.f;
        #pragma unroll 16
        for (int d = 0; d < 64; d++) acc += qrow[w][d]*ks[d*32+lane];
        g_sim[((size_t)bh*HWd+hw)*32+lane] =
            acc*0.044194173824159216f + 10000.f*mk[lane] - 10000.f;
        __syncwarp();
    }
}

// ---------------- lang->image softmax stats over HW ----------------
__global__ void latt_stats_kernel()
{
    const int bh = blockIdx.x, n = threadIdx.x, ty = threadIdx.y;
    float m = -1e30f, s = 0.f;
    for (int hw = ty; hw < HWd; hw += 32){
        float v = g_sim[((size_t)bh*HWd+hw)*32 + n];
        float nm = fmaxf(m, v);
        s = s*__expf(m-nm) + __expf(v-nm); m = nm;
    }
    __shared__ float sm_[32][33], ss[32][33];
    sm_[ty][n]=m; ss[ty][n]=s;
    __syncthreads();
    if (ty == 0){
        for (int i = 1; i < 32; i++){
            float m2=sm_[i][n], s2=ss[i][n], nm=fmaxf(m,m2);
            s = s*__expf(m-nm) + s2*__expf(m2-nm); m = nm;
        }
        g_lmax[bh*32+n]=m; g_lsum[bh*32+n]=s;
    }
}

// ---------------- image->lang: att_out = softmax_n(sim) . v  (bf16 hi/lo out) ----
__global__ __launch_bounds__(256) void attout_kernel()
{
    __shared__ float v_s[32*68];
    const int bh=blockIdx.y, b=bh>>3, h=bh&7, t=threadIdx.x;
    for (int e=t;e<2048;e+=256) v_s[(e&31)*68+(e>>5)] = g_v[((size_t)b*Vch + h*64)*NLd + e];
    __syncthreads();
    const int hw = blockIdx.x*256 + t;
    const float4* sp = (const float4*)&g_sim[((size_t)bh*HWd+hw)*32];
    float sv[32];
    #pragma unroll
    for (int j=0;j<8;j++){ float4 s4=sp[j]; sv[4*j]=s4.x; sv[4*j+1]=s4.y; sv[4*j+2]=s4.z; sv[4*j+3]=s4.w; }
    float mx=-1e30f;
    #pragma unroll
    for (int i=0;i<32;i++) mx=fmaxf(mx,sv[i]);
    float sum=0.f;
    #pragma unroll
    for (int i=0;i<32;i++){ sv[i]=__expf(sv[i]-mx); sum+=sv[i]; }
    float inv=1.f/sum;
    float acc[64];
    #pragma unroll
    for (int i=0;i<64;i++) acc[i]=0.f;
    #pragma unroll 4
    for (int n=0;n<32;n++){
        float a = sv[n]*inv;
        const float4* vr = (const float4*)&v_s[n*68];
        #pragma unroll
        for (int j=0;j<16;j++){
            float4 vv = vr[j];
            acc[4*j]+=a*vv.x; acc[4*j+1]+=a*vv.y; acc[4*j+2]+=a*vv.z; acc[4*j+3]+=a*vv.w;
        }
    }
    size_t base = (size_t)(b*HWd+hw)*Vch + h*64;
    #pragma unroll
    for (int j=0;j<16;j++){
        __nv_bfloat162 hp, lp;
        float a0=acc[4*j], a1=acc[4*j+1], a2=acc[4*j+2], a3=acc[4*j+3];
        hp.x=__float2bfloat16(a0); hp.y=__float2bfloat16(a1);
        lp.x=__float2bfloat16(a0-__bfloat162float(hp.x)); lp.y=__float2bfloat16(a1-__bfloat162float(hp.y));
        __nv_bfloat162 hq, lq;
        hq.x=__float2bfloat16(a2); hq.y=__float2bfloat16(a3);
        lq.x=__float2bfloat16(a2-__bfloat162float(hq.x)); lq.y=__float2bfloat16(a3-__bfloat162float(hq.y));
        *(uint2*)(g_ath+base+4*j) = make_uint2(*(uint32_t*)&hp, *(uint32_t*)&hq);
        *(uint2*)(g_atl+base+4*j) = make_uint2(*(uint32_t*)&lp, *(uint32_t*)&lq);
    }
}

// ---------------- lang_out partials: latt . inorm(lv) over an HW slice ----------
__global__ __launch_bounds__(256) void langout_part_kernel()
{
    __shared__ float ps[32*32];
    __shared__ float lvs[32*96];
    __shared__ float lmx[32], lsm[32];
    const int bh=blockIdx.x, spl=blockIdx.y, b=bh>>3, h=bh&7, t=threadIdx.x;
    if (t<32){ lmx[t]=g_lmax[bh*32+t]; lsm[t]=1.f/g_lsum[bh*32+t]; }
    __syncthreads();
    const int n=t&31, c0=(t>>5)*12;
    float acc[12];
    #pragma unroll
    for (int j=0;j<12;j++) acc[j]=0.f;
    const int hwA = spl*(HWd/SPL), hwB = hwA + HWd/SPL;
    for (int hw0=hwA; hw0<hwB; hw0+=32){
        for (int e=t;e<1024;e+=256){
            int r=e>>5, nn=e&31;
            ps[e]=__expf(g_sim[((size_t)bh*HWd+hw0+r)*32+nn]-lmx[nn])*lsm[nn];
        }
        for (int e=t;e<3072;e+=256){
            int r=e/96, cc=e-r*96, ch=h*96+cc;
            lvs[e]=(g_lv[((size_t)(b*HWd+hw0+r))*CLd+ch]-g_mlv[b*CLd+ch])*g_rlv[b*CLd+ch];
        }
        __syncthreads();
        #pragma unroll 8
        for (int r=0;r<32;r++){
            float p=ps[r*32+n];
            #pragma unroll
            for (int j=0;j<12;j++) acc[j]+=p*lvs[r*96+c0+j];
        }
        __syncthreads();
    }
    #pragma unroll
    for (int j=0;j<12;j++)
        g_lop[spl][((size_t)b*CLd + h*96+c0+j)*NLd + n] = acc[j];
}

// ---------------- reduce partials + mask -> g_lo1 ----------------
__global__ void lo1_reduce_kernel(const float* __restrict__ mask)
{
    const int idx = blockIdx.x*256 + threadIdx.x;
    float s = 0.f;
    #pragma unroll
    for (int p = 0; p < SPL; p++) s += g_lop[p][idx];
    int n = idx & 31, b = idx / (CLd*NLd);
    g_lo1[idx] = s * mask[b*NLd + n];
}

// ---------------- z = vis * inorm(vo)  ->  bf16 hi/lo ----------------
__global__ void zmul_kernel()
{
    size_t i = ((size_t)blockIdx.x*256 + threadIdx.x)*4;
    int c = (int)(i & 511);
    int b = (int)((i >> 9) >> 12);
    float4 vi = *(const float4*)&g_vis[i];
    float4 vo = *(const float4*)&g_vo[i];
    float z0 = vi.x*(vo.x-g_mw[b*Vch+c  ])*g_rw[b*Vch+c  ];
    float z1 = vi.y*(vo.y-g_mw[b*Vch+c+1])*g_rw[b*Vch+c+1];
    float z2 = vi.z*(vo.z-g_mw[b*Vch+c+2])*g_rw[b*Vch+c+2];
    float z3 = vi.w*(vo.w-g_mw[b*Vch+c+3])*g_rw[b*Vch+c+3];
    __nv_bfloat162 hp, hq, lp, lq;
    hp.x=__float2bfloat16(z0); hp.y=__float2bfloat16(z1);
    hq.x=__float2bfloat16(z2); hq.y=__float2bfloat16(z3);
    lp.x=__float2bfloat16(z0-__bfloat162float(hp.x)); lp.y=__float2bfloat16(z1-__bfloat162float(hp.y));
    lq.x=__float2bfloat16(z2-__bfloat162float(hq.x)); lq.y=__float2bfloat16(z3-__bfloat162float(hq.y));
    *(uint2*)(g_zh+i) = make_uint2(*(uint32_t*)&hp, *(uint32_t*)&hq);
    *(uint2*)(g_zl+i) = make_uint2(*(uint32_t*)&lp, *(uint32_t*)&lq);
}

// ---------------- elementwise: zt = lang * lang_out2 ----------------
__global__ void ztmul_kernel()
{
    size_t i = ((size_t)blockIdx.x*256 + threadIdx.x)*4;
    float4 a = *(const float4*)&g_lang[i];
    float4 b4 = *(const float4*)&g_lo2[i];
    float4 r; r.x=a.x*b4.x; r.y=a.y*b4.y; r.z=a.z*b4.z; r.w=a.w*b4.w;
    *(float4*)&g_zt[i] = r;
}

extern "C" void kernel_launch(void* const* d_in, const int* in_sizes, int n_in,
                              void* d_out, int out_size)
{
    const float* x      = (const float*)d_in[0];
    const float* l      = (const float*)d_in[1];
    const float* lmask  = (const float*)d_in[2];
    const float* w_vis  = (const float*)d_in[3];  const float* b_vis  = (const float*)d_in[4];
    const float* w_langp= (const float*)d_in[5];  const float* b_langp= (const float*)d_in[6];
    const float* w_q    = (const float*)d_in[7];  const float* b_q    = (const float*)d_in[8];
    const float* w_k    = (const float*)d_in[9];  const float* b_k    = (const float*)d_in[10];
    const float* w_v    = (const float*)d_in[11]; const float* b_v    = (const float*)d_in[12];
    const float* w_lv   = (const float*)d_in[13]; const float* b_lv   = (const float*)d_in[14];
    const float* w_W    = (const float*)d_in[15]; const float* b_W    = (const float*)d_in[16];
    const float* w_langW= (const float*)d_in[17]; const float* b_langW= (const float*)d_in[18];
    const float* w_mm   = (const float*)d_in[19]; const float* b_mm   = (const float*)d_in[20];
    const float* w_langmm=(const float*)d_in[21]; const float* b_langmm=(const float*)d_in[22];
    float* out = (float*)d_out;

    float *p_vis, *p_q, *p_lv, *p_vo, *p_lang, *p_k, *p_v, *p_lo1, *p_lo2, *p_zt;
    float *p_mq, *p_rq, *p_mlv, *p_rlv, *p_mw, *p_rw;
    __nv_bfloat16 *p_xh, *p_xl, *p_ath, *p_atl, *p_zh, *p_zl, *p_wh, *p_wl;
    cudaGetSymbolAddress((void**)&p_vis, g_vis);  cudaGetSymbolAddress((void**)&p_q,  g_q);
    cudaGetSymbolAddress((void**)&p_lv,  g_lv);   cudaGetSymbolAddress((void**)&p_vo, g_vo);
    cudaGetSymbolAddress((void**)&p_lang,g_lang); cudaGetSymbolAddress((void**)&p_k,  g_k);
    cudaGetSymbolAddress((void**)&p_v,   g_v);    cudaGetSymbolAddress((void**)&p_lo1,g_lo1);
    cudaGetSymbolAddress((void**)&p_lo2, g_lo2);  cudaGetSymbolAddress((void**)&p_zt, g_zt);
    cudaGetSymbolAddress((void**)&p_mq,  g_mq);   cudaGetSymbolAddress((void**)&p_rq, g_rq);
    cudaGetSymbolAddress((void**)&p_mlv, g_mlv);  cudaGetSymbolAddress((void**)&p_rlv,g_rlv);
    cudaGetSymbolAddress((void**)&p_mw,  g_mw);   cudaGetSymbolAddress((void**)&p_rw, g_rw);
    cudaGetSymbolAddress((void**)&p_xh,  g_xh);   cudaGetSymbolAddress((void**)&p_xl, g_xl);
    cudaGetSymbolAddress((void**)&p_ath, g_ath);  cudaGetSymbolAddress((void**)&p_atl,g_atl);
    cudaGetSymbolAddress((void**)&p_zh,  g_zh);   cudaGetSymbolAddress((void**)&p_zl, g_zl);
    cudaGetSymbolAddress((void**)&p_wh,  g_wh);   cudaGetSymbolAddress((void**)&p_wl, g_wl);

    cudaFuncSetAttribute(tc_gemm, cudaFuncAttributeMaxDynamicSharedMemorySize, SMEMB);

    dim3 blk256(256);
    // pre-convert x + weights to bf16 hi/lo
    cvt_split<<<(int)(((size_t)Mm*Dd)/1024), blk256>>>(x, p_xh, p_xl);
    cvt_split<<<262144/1024, blk256>>>(w_vis, p_wh+WOFF_VIS, p_wl+WOFF_VIS);
    cvt_split<<<262144/1024, blk256>>>(w_q,   p_wh+WOFF_Q,   p_wl+WOFF_Q);
    cvt_split<<<393216/1024, blk256>>>(w_lv,  p_wh+WOFF_LV,  p_wl+WOFF_LV);
    cvt_split<<<262144/1024, blk256>>>(w_W,   p_wh+WOFF_W,   p_wl+WOFF_W);
    cvt_split<<<262144/1024, blk256>>>(w_mm,  p_wh+WOFF_MM,  p_wl+WOFF_MM);
    // big GEMMs
    tc_gemm<<<dim3(Dd/128,  Mm/128), blk256, SMEMB>>>(p_xh, p_xl, p_wh+WOFF_VIS, p_wl+WOFF_VIS, b_vis, p_vis, Dd,  Dd, 1);
    tc_gemm<<<dim3(Kch/128, Mm/128), blk256, SMEMB>>>(p_xh, p_xl, p_wh+WOFF_Q,   p_wl+WOFF_Q,   b_q,   p_q,   Kch, Dd, 0);
    tc_gemm<<<dim3(CLd/128, Mm/128), blk256, SMEMB>>>(p_xh, p_xl, p_wh+WOFF_LV,  p_wl+WOFF_LV,  b_lv,  p_lv,  CLd, Dd, 0);
    stats_kernel<<<dim3(Kch/32, Bb), dim3(32,16)>>>(p_q,  p_mq,  p_rq,  Kch);
    stats_kernel<<<dim3(CLd/32, Bb), dim3(32,16)>>>(p_lv, p_mlv, p_rlv, CLd);
    // lang-side convs
    lang_conv_kernel<<<dim3(Bb, CLd/32), blk256>>>(l, w_langp, b_langp, lmask, p_lang, CLd, 1);
    lang_conv_kernel<<<dim3(Bb, Kch/32), blk256>>>(l, w_k, b_k, lmask, p_k, Kch, 2);
    lang_conv_kernel<<<dim3(Bb, Vch/32), blk256>>>(l, w_v, b_v, lmask, p_v, Vch, 2);
    // attention
    sim_kernel<<<dim3(HWd/1024, Bb*Hh), blk256>>>(lmask);
    latt_stats_kernel<<<Bb*Hh, dim3(32,32)>>>();
    attout_kernel<<<dim3(HWd/256, Bb*Hh), blk256>>>();
    langout_part_kernel<<<dim3(Bb*Hh, SPL), blk256>>>();
    lo1_reduce_kernel<<<(Bb*CLd*NLd)/256, blk256>>>(lmask);
    // lang_out2 = inorm(conv(lang_out, w_langW))
    lang_conv_kernel<<<dim3(Bb, CLd/32), blk256>>>(p_lo1, w_langW, b_langW, lmask, p_lo2, CLd, 8);
    // vis_out = inorm(conv(att_out, w_W))
    tc_gemm<<<dim3(Vch/128, Mm/128), blk256, SMEMB>>>(p_ath, p_atl, p_wh+WOFF_W, p_wl+WOFF_W, b_W, p_vo, Vch, Vch, 0);
    stats_kernel<<<dim3(Vch/32, Bb), dim3(32,16)>>>(p_vo, p_mw, p_rw, Vch);
    zmul_kernel<<<(int)(((size_t)Mm*Vch)/1024), blk256>>>();
    // mm = gelu(conv(z, w_mm)) -> out[0 : M*V]
    tc_gemm<<<dim3(Vch/128, Mm/128), blk256, SMEMB>>>(p_zh, p_zl, p_wh+WOFF_MM, p_wl+WOFF_MM, b_mm, out, Vch, Vch, 1);
    // lang_mm = gelu(conv(lang*lo2, w_langmm)) transposed -> out tail
    ztmul_kernel<<<(Bb*CLd*NLd)/1024, blk256>>>();
    lang_conv_kernel<<<dim3(Bb, CLd/32), blk256>>>(p_zt, w_langmm, b_langmm, lmask,
                                                   out + (size_t)Mm*Vch, CLd, 1|4);
    (void)in_sizes; (void)n_in; (void)out_size;
}

// round 14
// speedup vs baseline: 1.7148x; 1.0652x over previous
#include <cuda_runtime.h>
#include <cuda_bf16.h>
#include <math.h>
#include <stdint.h>

#define Bb   16
#define HWd  4096
#define Dd   512
#define CLd  768
#define Kch  512
#define Vch  512
#define NLd  32
#define Hh   8
#define Mm   (Bb*HWd)
#define SPL  8

// ---------------- scratch ----------------
static __device__ float g_vis[(size_t)Mm*Dd];
static __device__ float g_q  [(size_t)Mm*Kch];
static __device__ float g_lv [(size_t)Mm*CLd];
static __device__ float g_vo [(size_t)Mm*Vch];
static __device__ float g_sim[(size_t)Bb*Hh*HWd*NLd];
static __device__ __nv_bfloat16 g_xh[(size_t)Mm*Dd],  g_xl[(size_t)Mm*Dd];
static __device__ __nv_bfloat16 g_ath[(size_t)Mm*Vch], g_atl[(size_t)Mm*Vch];
static __device__ __nv_bfloat16 g_zh[(size_t)Mm*Vch],  g_zl[(size_t)Mm*Vch];
#define WOFF_VIS 0
#define WOFF_Q   262144
#define WOFF_LV  524288
#define WOFF_W   917504
#define WOFF_MM  1179648
static __device__ __nv_bfloat16 g_wh[1441792], g_wl[1441792];
static __device__ float g_lang[Bb*CLd*NLd];
static __device__ float g_k  [Bb*Kch*NLd];
static __device__ float g_v  [Bb*Vch*NLd];
static __device__ float g_lop[SPL][Bb*CLd*NLd];
static __device__ float g_lo1[Bb*CLd*NLd];
static __device__ float g_lo2[Bb*CLd*NLd];
static __device__ float g_zt [Bb*CLd*NLd];
static __device__ float g_mq [Bb*Kch],  g_rq [Bb*Kch];
static __device__ float g_mlv[Bb*CLd],  g_rlv[Bb*CLd];
static __device__ float g_mw [Bb*Vch],  g_rw [Bb*Vch];
static __device__ float g_lmax[Bb*Hh*NLd], g_lsum[Bb*Hh*NLd];

__device__ __forceinline__ float gelu_f(float x){
    return 0.5f*x*(1.0f + erff(x*0.70710678118654752f));
}
__device__ __forceinline__ uint32_t smem_u32(const void* p){
    uint32_t a;
    asm("{ .reg .u64 t; cvta.to.shared.u64 t, %1; cvt.u32.u64 %0, t; }" : "=r"(a) : "l"(p));
    return a;
}
__device__ __forceinline__ void cp16(uint32_t s, const void* g){
    asm volatile("cp.async.cg.shared.global [%0], [%1], 16;" :: "r"(s), "l"(g));
}
__device__ __forceinline__ void mma16816(float* c, const uint32_t* a, const uint32_t* b){
    asm volatile("mma.sync.aligned.m16n8k16.row.col.f32.bf16.bf16.f32 "
        "{%0,%1,%2,%3}, {%4,%5,%6,%7}, {%8,%9}, {%0,%1,%2,%3};"
        : "+f"(c[0]),"+f"(c[1]),"+f"(c[2]),"+f"(c[3])
        : "r"(a[0]),"r"(a[1]),"r"(a[2]),"r"(a[3]), "r"(b[0]),"r"(b[1]));
}

// ---------------- fp32 -> bf16 hi/lo split ----------------
__global__ void cvt_split(const float* __restrict__ src,
                          __nv_bfloat16* __restrict__ hi, __nv_bfloat16* __restrict__ lo)
{
    size_t i = ((size_t)blockIdx.x*256 + threadIdx.x)*4;
    float4 v = *(const float4*)(src + i);
    __nv_bfloat16 h0=__float2bfloat16(v.x), h1=__float2bfloat16(v.y);
    __nv_bfloat16 h2=__float2bfloat16(v.z), h3=__float2bfloat16(v.w);
    __nv_bfloat162 hp0; hp0.x=h0; hp0.y=h1;
    __nv_bfloat162 hp1; hp1.x=h2; hp1.y=h3;
    *(uint2*)(hi+i) = make_uint2(*(uint32_t*)&hp0, *(uint32_t*)&hp1);
    __nv_bfloat162 lp0, lp1;
    lp0.x=__float2bfloat16(v.x-__bfloat162float(h0)); lp0.y=__float2bfloat16(v.y-__bfloat162float(h1));
    lp1.x=__float2bfloat16(v.z-__bfloat162float(h2)); lp1.y=__float2bfloat16(v.w-__bfloat162float(h3));
    *(uint2*)(lo+i) = make_uint2(*(uint32_t*)&lp0, *(uint32_t*)&lp1);
}

// ---------------- multistage HMMA GEMM (bf16 hi/lo, scalar frag loads) ----------------
#define BUFB 10240
#define STGB (4*BUFB)
#define NSTG 2
#define SMEMB (NSTG*STGB)

__device__ __forceinline__ void issue_stage(
    uint32_t sb, const __nv_bfloat16* Ah, const __nv_bfloat16* Al,
    const __nv_bfloat16* Wh, const __nv_bfloat16* Wl,
    int K, int m0, int n0, int k0, int t)
{
    #pragma unroll
    for (int i = 0; i < 2; i++){
        int q = t + i*256;
        int row = q >> 2, seg = q & 3;
        uint32_t so = row*80 + seg*16;
        size_t ga = (size_t)(m0+row)*K + k0 + seg*8;
        size_t gw = (size_t)(n0+row)*K + k0 + seg*8;
        cp16(sb + so,          Ah + ga);
        cp16(sb + BUFB + so,   Al + ga);
        cp16(sb + 2*BUFB + so, Wh + gw);
        cp16(sb + 3*BUFB + so, Wl + gw);
    }
}

__global__ __launch_bounds__(256) void tc_gemm(
    const __nv_bfloat16* __restrict__ Ah, const __nv_bfloat16* __restrict__ Al,
    const __nv_bfloat16* __restrict__ Wh, const __nv_bfloat16* __restrict__ Wl,
    const float* __restrict__ bias, float* __restrict__ C, int N, int K, int act)
{
    extern __shared__ char sm[];
    const uint32_t smb = smem_u32(sm);
    const int t = threadIdx.x, lane = t & 31, wid = t >> 5;
    const int m0 = blockIdx.y * 128, n0 = blockIdx.x * 128;
    const int wm = (wid & 3) * 32, wn = (wid >> 2) * 64;
    const int fr_ = lane >> 2, fc = (lane & 3) * 2;

    float acc[2][8][4];
    #pragma unroll
    for (int i=0;i<2;i++)
        #pragma unroll
        for (int j=0;j<8;j++){ acc[i][j][0]=0.f; acc[i][j][1]=0.f; acc[i][j][2]=0.f; acc[i][j][3]=0.f; }

    const int niter = K >> 5;
    issue_stage(smb, Ah, Al, Wh, Wl, K, m0, n0, 0, t);
    asm volatile("cp.async.commit_group;");

    for (int it = 0; it < niter; it++){
        if (it + 1 < niter){
            issue_stage(smb + ((it+1)&1)*STGB, Ah, Al, Wh, Wl, K, m0, n0, (it+1)<<5, t);
            asm volatile("cp.async.commit_group;");
            asm volatile("cp.async.wait_group 1;");
        } else {
            asm volatile("cp.async.wait_group 0;");
        }
        __syncthreads();

        const char* sb = sm + (it&1)*STGB;
        const char* sa_h = sb;
        const char* sa_l = sb + BUFB;
        const char* sw_h = sb + 2*BUFB;
        const char* sw_l = sb + 3*BUFB;

        #pragma unroll
        for (int ks = 0; ks < 2; ks++){
            const int kk = ks * 16;
            uint32_t ah[2][4], al[2][4];
            #pragma unroll
            for (int mi = 0; mi < 2; mi++){
                int r = wm + mi * 16 + fr_;
                ah[mi][0] = *(const uint32_t*)(sa_h + (r    )*80 + (kk+fc)*2);
                ah[mi][1] = *(const uint32_t*)(sa_h + (r + 8)*80 + (kk+fc)*2);
                ah[mi][2] = *(const uint32_t*)(sa_h + (r    )*80 + (kk+fc+8)*2);
                ah[mi][3] = *(const uint32_t*)(sa_h + (r + 8)*80 + (kk+fc+8)*2);
                al[mi][0] = *(const uint32_t*)(sa_l + (r    )*80 + (kk+fc)*2);
                al[mi][1] = *(const uint32_t*)(sa_l + (r + 8)*80 + (kk+fc)*2);
                al[mi][2] = *(const uint32_t*)(sa_l + (r    )*80 + (kk+fc+8)*2);
                al[mi][3] = *(const uint32_t*)(sa_l + (r + 8)*80 + (kk+fc+8)*2);
            }
            uint32_t bh[8][2], bl[8][2];
            #pragma unroll
            for (int ni = 0; ni < 8; ni++){
                int n = wn + ni * 8 + fr_;
                bh[ni][0] = *(const uint32_t*)(sw_h + n*80 + (kk+fc)*2);
                bh[ni][1] = *(const uint32_t*)(sw_h + n*80 + (kk+fc+8)*2);
                bl[ni][0] = *(const uint32_t*)(sw_l + n*80 + (kk+fc)*2);
                bl[ni][1] = *(const uint32_t*)(sw_l + n*80 + (kk+fc+8)*2);
            }
            #pragma unroll
            for (int mi = 0; mi < 2; mi++)
                #pragma unroll
                for (int ni = 0; ni < 8; ni++){
                    mma16816(acc[mi][ni], ah[mi], bh[ni]);
                    mma16816(acc[mi][ni], ah[mi], bl[ni]);
                    mma16816(acc[mi][ni], al[mi], bh[ni]);
                }
        }
        __syncthreads();
    }

    #pragma unroll
    for (int mi = 0; mi < 2; mi++){
        #pragma unroll
        for (int ni = 0; ni < 8; ni++){
            int m = m0 + wm + mi * 16 + fr_;
            int n = n0 + wn + ni * 8 + fc;
            float b0 = bias[n], b1 = bias[n + 1];
            float v0 = acc[mi][ni][0] + b0, v1 = acc[mi][ni][1] + b1;
            float v2 = acc[mi][ni][2] + b0, v3 = acc[mi][ni][3] + b1;
            if (act){ v0 = gelu_f(v0); v1 = gelu_f(v1); v2 = gelu_f(v2); v3 = gelu_f(v3); }
            *(float2*)&C[(size_t)m * N + n]       = make_float2(v0, v1);
            *(float2*)&C[(size_t)(m + 8) * N + n] = make_float2(v2, v3);
        }
    }
}

// ---------------- per-(b,c) mean/rstd over HW (fp32, unrolled loads) ----------------
__global__ void stats_kernel(const float* __restrict__ A, float* __restrict__ mean,
                             float* __restrict__ rstd, int C)
{
    const int b = blockIdx.y, c = blockIdx.x*32 + threadIdx.x, ty = threadIdx.y;
    const float* base = A + (size_t)b*HWd*C + c;
    float s=0.f, s2=0.f;
    #pragma unroll 8
    for (int hw=ty; hw<HWd; hw+=16){ float v = base[(size_t)hw*C]; s+=v; s2+=v*v; }
    __shared__ float ss[16][33], sq[16][33];
    ss[ty][threadIdx.x]=s; sq[ty][threadIdx.x]=s2;
    __syncthreads();
    if (ty==0){
        #pragma unroll
        for (int i=1;i<16;i++){ s+=ss[i][threadIdx.x]; s2+=sq[i][threadIdx.x]; }
        float m = s*(1.f/HWd), var = s2*(1.f/HWd) - m*m;
        mean[b*C+c]=m; rstd[b*C+c]=rsqrtf(var + 1e-5f);
    }
}

// ---------------- lang 1x1 conv: mode 1 gelu, 2 mask, 4 transpose, 8 inorm(NL) ----
__global__ __launch_bounds__(256) void lang_conv_kernel(
    const float* __restrict__ in, const float* __restrict__ w,
    const float* __restrict__ bias, const float* __restrict__ mask,
    float* __restrict__ out, int Cout, int mode)
{
    __shared__ float in_s[32][33];
    __shared__ float w_s [32][33];
    const int b = blockIdx.x, o0 = blockIdx.y*32, t = threadIdx.x;
    const int n = t & 31, og = t >> 5;
    float acc[4] = {0.f,0.f,0.f,0.f};
    for (int i0 = 0; i0 < CLd; i0 += 32){
        for (int e = t; e < 1024; e += 256) in_s[e>>5][e&31] = in[((size_t)b*CLd + i0+(e>>5))*NLd + (e&31)];
        for (int e = t; e < 1024; e += 256) w_s[e>>5][e&31]  = w[(size_t)(o0+(e>>5))*CLd + i0+(e&31)];
        __syncthreads();
        #pragma unroll
        for (int ii = 0; ii < 32; ii++){
            float iv = in_s[ii][n];
            acc[0]+=w_s[og   ][ii]*iv; acc[1]+=w_s[og+ 8][ii]*iv;
            acc[2]+=w_s[og+16][ii]*iv; acc[3]+=w_s[og+24][ii]*iv;
        }
        __syncthreads();
    }
    float mv = (mode & 2) ? mask[b*NLd + n] : 1.f;
    #pragma unroll
    for (int j = 0; j < 4; j++){
        int o = o0 + og + 8*j;
        float v = acc[j] + bias[o];
        if (mode & 2) v *= mv;
        if (mode & 8){
            float s=v, s2=v*v;
            #pragma unroll
            for (int off=16;off;off>>=1){ s+=__shfl_xor_sync(~0u,s,off); s2+=__shfl_xor_sync(~0u,s2,off); }
            float mn = s*(1.f/32.f), vr = s2*(1.f/32.f) - mn*mn;
            v = (v-mn)*rsqrtf(vr + 1e-5f);
        }
        if (mode & 1) v = gelu_f(v);
        if (mode & 4) out[((size_t)b*NLd + n)*Cout + o] = v;
        else          out[((size_t)b*Cout + o)*NLd + n] = v;
    }
}

// ---------------- sim = inorm(q).k * scale + 1e4*mask - 1e4 ----------------
__global__ __launch_bounds__(256) void sim_kernel(const float* __restrict__ mask)
{
    __shared__ float ks[64*32];
    __shared__ float qm[64], qr[64], mk[32];
    __shared__ float qrow[8][64];
    const int bh = blockIdx.y, b = bh>>3, h = bh&7;
    const int t = threadIdx.x, w = t>>5, lane = t&31;
    for (int e = t; e < 2048; e += 256) ks[e] = g_k[((size_t)b*Kch + h*64)*NLd + e];
    if (t < 64){ qm[t]=g_mq[b*Kch+h*64+t]; qr[t]=g_rq[b*Kch+h*64+t]; }
    if (t >= 64 && t < 96) mk[t-64]=mask[b*NLd+t-64];
    __syncthreads();
    const int hw0 = blockIdx.x*1024;
    for (int it = 0; it < 128; it++){
        int hw = hw0 + it*8 + w;
        const float2 q2 = ((const float2*)&g_q[((size_t)(b*HWd+hw))*Kch + h*64])[lane];
        qrow[w][2*lane  ] = (q2.x - qm[2*lane  ])*qr[2*lane  ];
        qrow[w][2*lane+1] = (q2.y - qm[2*lane+1])*qr[2*lane+1];
        __syncwarp();
        float acc = 0.f;
        #pragma unroll 16
        for (int d = 0; d < 64; d++) acc += qrow[w][d]*ks[d*32+lane];
        g_sim[((size_t)bh*HWd+hw)*32+lane] =
            acc*0.044194173824159216f + 10000.f*mk[lane] - 10000.f;
        __syncwarp();
    }
}

// ---------------- lang->image softmax stats over HW ----------------
__global__ void latt_stats_kernel()
{
    const int bh = blockIdx.x, n = threadIdx.x, ty = threadIdx.y;
    float m = -1e30f, s = 0.f;
    for (int hw = ty; hw < HWd; hw += 32){
        float v = g_sim[((size_t)bh*HWd+hw)*32 + n];
        float nm = fmaxf(m, v);
        s = s*__expf(m-nm) + __expf(v-nm); m = nm;
    }
    __shared__ float sm_[32][33], ss[32][33];
    sm_[ty][n]=m; ss[ty][n]=s;
    __syncthreads();
    if (ty == 0){
        for (int i = 1; i < 32; i++){
            float m2=sm_[i][n], s2=ss[i][n], nm=fmaxf(m,m2);
            s = s*__expf(m-nm) + s2*__expf(m2-nm); m = nm;
        }
        g_lmax[bh*32+n]=m; g_lsum[bh*32+n]=s;
    }
}

// ---------------- image->lang: att_out = softmax_n(sim) . v  (bf16 hi/lo out) ----
__global__ __launch_bounds__(256) void attout_kernel()
{
    __shared__ float v_s[32*68];
    const int bh=blockIdx.y, b=bh>>3, h=bh&7, t=threadIdx.x;
    for (int e=t;e<2048;e+=256) v_s[(e&31)*68+(e>>5)] = g_v[((size_t)b*Vch + h*64)*NLd + e];
    __syncthreads();
    const int hw = blockIdx.x*256 + t;
    const float4* sp = (const float4*)&g_sim[((size_t)bh*HWd+hw)*32];
    float sv[32];
    #pragma unroll
    for (int j=0;j<8;j++){ float4 s4=sp[j]; sv[4*j]=s4.x; sv[4*j+1]=s4.y; sv[4*j+2]=s4.z; sv[4*j+3]=s4.w; }
    float mx=-1e30f;
    #pragma unroll
    for (int i=0;i<32;i++) mx=fmaxf(mx,sv[i]);
    float sum=0.f;
    #pragma unroll
    for (int i=0;i<32;i++){ sv[i]=__expf(sv[i]-mx); sum+=sv[i]; }
    float inv=1.f/sum;
    float acc[64];
    #pragma unroll
    for (int i=0;i<64;i++) acc[i]=0.f;
    #pragma unroll 4
    for (int n=0;n<32;n++){
        float a = sv[n]*inv;
        const float4* vr = (const float4*)&v_s[n*68];
        #pragma unroll
        for (int j=0;j<16;j++){
            float4 vv = vr[j];
            acc[4*j]+=a*vv.x; acc[4*j+1]+=a*vv.y; acc[4*j+2]+=a*vv.z; acc[4*j+3]+=a*vv.w;
        }
    }
    size_t base = (size_t)(b*HWd+hw)*Vch + h*64;
    #pragma unroll
    for (int j=0;j<16;j++){
        __nv_bfloat162 hp, lp;
        float a0=acc[4*j], a1=acc[4*j+1], a2=acc[4*j+2], a3=acc[4*j+3];
        hp.x=__float2bfloat16(a0); hp.y=__float2bfloat16(a1);
        lp.x=__float2bfloat16(a0-__bfloat162float(hp.x)); lp.y=__float2bfloat16(a1-__bfloat162float(hp.y));
        __nv_bfloat162 hq, lq;
        hq.x=__float2bfloat16(a2); hq.y=__float2bfloat16(a3);
        lq.x=__float2bfloat16(a2-__bfloat162float(hq.x)); lq.y=__float2bfloat16(a3-__bfloat162float(hq.y));
        *(uint2*)(g_ath+base+4*j) = make_uint2(*(uint32_t*)&hp, *(uint32_t*)&hq);
        *(uint2*)(g_atl+base+4*j) = make_uint2(*(uint32_t*)&lp, *(uint32_t*)&lq);
    }
}

// ---------------- lang_out partials: latt . inorm(lv) over an HW slice ----------
__global__ __launch_bounds__(256) void langout_part_kernel()
{
    __shared__ float ps[32*32];
    __shared__ float lvs[32*96];
    __shared__ float lmx[32], lsm[32];
    const int bh=blockIdx.x, spl=blockIdx.y, b=bh>>3, h=bh&7, t=threadIdx.x;
    if (t<32){ lmx[t]=g_lmax[bh*32+t]; lsm[t]=1.f/g_lsum[bh*32+t]; }
    __syncthreads();
    const int n=t&31, c0=(t>>5)*12;
    float acc[12];
    #pragma unroll
    for (int j=0;j<12;j++) acc[j]=0.f;
    const int hwA = spl*(HWd/SPL), hwB = hwA + HWd/SPL;
    for (int hw0=hwA; hw0<hwB; hw0+=32){
        for (int e=t;e<1024;e+=256){
            int r=e>>5, nn=e&31;
            ps[e]=__expf(g_sim[((size_t)bh*HWd+hw0+r)*32+nn]-lmx[nn])*lsm[nn];
        }
        for (int e=t;e<3072;e+=256){
            int r=e/96, cc=e-r*96, ch=h*96+cc;
            lvs[e]=(g_lv[((size_t)(b*HWd+hw0+r))*CLd+ch]-g_mlv[b*CLd+ch])*g_rlv[b*CLd+ch];
        }
        __syncthreads();
        #pragma unroll 8
        for (int r=0;r<32;r++){
            float p=ps[r*32+n];
            #pragma unroll
            for (int j=0;j<12;j++) acc[j]+=p*lvs[r*96+c0+j];
        }
        __syncthreads();
    }
    #pragma unroll
    for (int j=0;j<12;j++)
        g_lop[spl][((size_t)b*CLd + h*96+c0+j)*NLd + n] = acc[j];
}

// ---------------- reduce partials + mask -> g_lo1 ----------------
__global__ void lo1_reduce_kernel(const float* __restrict__ mask)
{
    const int idx = blockIdx.x*256 + threadIdx.x;
    float s = 0.f;
    #pragma unroll
    for (int p = 0; p < SPL; p++) s += g_lop[p][idx];
    int n = idx & 31, b = idx / (CLd*NLd);
    g_lo1[idx] = s * mask[b*NLd + n];
}

// ---------------- z = vis * inorm(vo)  ->  bf16 hi/lo ----------------
__global__ void zmul_kernel()
{
    size_t i = ((size_t)blockIdx.x*256 + threadIdx.x)*4;
    int c = (int)(i & 511);
    int b = (int)((i >> 9) >> 12);
    float4 vi = *(const float4*)&g_vis[i];
    float4 vo = *(const float4*)&g_vo[i];
    float z0 = vi.x*(vo.x-g_mw[b*Vch+c  ])*g_rw[b*Vch+c  ];
    float z1 = vi.y*(vo.y-g_mw[b*Vch+c+1])*g_rw[b*Vch+c+1];
    float z2 = vi.z*(vo.z-g_mw[b*Vch+c+2])*g_rw[b*Vch+c+2];
    float z3 = vi.w*(vo.w-g_mw[b*Vch+c+3])*g_rw[b*Vch+c+3];
    __nv_bfloat162 hp, hq, lp, lq;
    hp.x=__float2bfloat16(z0); hp.y=__float2bfloat16(z1);
    hq.x=__float2bfloat16(z2); hq.y=__float2bfloat16(z3);
    lp.x=__float2bfloat16(z0-__bfloat162float(hp.x)); lp.y=__float2bfloat16(z1-__bfloat162float(hp.y));
    lq.x=__float2bfloat16(z2-__bfloat162float(hq.x)); lq.y=__float2bfloat16(z3-__bfloat162float(hq.y));
    *(uint2*)(g_zh+i) = make_uint2(*(uint32_t*)&hp, *(uint32_t*)&hq);
    *(uint2*)(g_zl+i) = make_uint2(*(uint32_t*)&lp, *(uint32_t*)&lq);
}

// ---------------- elementwise: zt = lang * lang_out2 ----------------
__global__ void ztmul_kernel()
{
    size_t i = ((size_t)blockIdx.x*256 + threadIdx.x)*4;
    float4 a = *(const float4*)&g_lang[i];
    float4 b4 = *(const float4*)&g_lo2[i];
    float4 r; r.x=a.x*b4.x; r.y=a.y*b4.y; r.z=a.z*b4.z; r.w=a.w*b4.w;
    *(float4*)&g_zt[i] = r;
}

extern "C" void kernel_launch(void* const* d_in, const int* in_sizes, int n_in,
                              void* d_out, int out_size)
{
    const float* x      = (const float*)d_in[0];
    const float* l      = (const float*)d_in[1];
    const float* lmask  = (const float*)d_in[2];
    const float* w_vis  = (const float*)d_in[3];  const float* b_vis  = (const float*)d_in[4];
    const float* w_langp= (const float*)d_in[5];  const float* b_langp= (const float*)d_in[6];
    const float* w_q    = (const float*)d_in[7];  const float* b_q    = (const float*)d_in[8];
    const float* w_k    = (const float*)d_in[9];  const float* b_k    = (const float*)d_in[10];
    const float* w_v    = (const float*)d_in[11]; const float* b_v    = (const float*)d_in[12];
    const float* w_lv   = (const float*)d_in[13]; const float* b_lv   = (const float*)d_in[14];
    const float* w_W    = (const float*)d_in[15]; const float* b_W    = (const float*)d_in[16];
    const float* w_langW= (const float*)d_in[17]; const float* b_langW= (const float*)d_in[18];
    const float* w_mm   = (const float*)d_in[19]; const float* b_mm   = (const float*)d_in[20];
    const float* w_langmm=(const float*)d_in[21]; const float* b_langmm=(const float*)d_in[22];
    float* out = (float*)d_out;

    float *p_vis, *p_q, *p_lv, *p_vo, *p_lang, *p_k, *p_v, *p_lo1, *p_lo2, *p_zt;
    float *p_mq, *p_rq, *p_mlv, *p_rlv, *p_mw, *p_rw;
    __nv_bfloat16 *p_xh, *p_xl, *p_ath, *p_atl, *p_zh, *p_zl, *p_wh, *p_wl;
    cudaGetSymbolAddress((void**)&p_vis, g_vis);  cudaGetSymbolAddress((void**)&p_q,  g_q);
    cudaGetSymbolAddress((void**)&p_lv,  g_lv);   cudaGetSymbolAddress((void**)&p_vo, g_vo);
    cudaGetSymbolAddress((void**)&p_lang,g_lang); cudaGetSymbolAddress((void**)&p_k,  g_k);
    cudaGetSymbolAddress((void**)&p_v,   g_v);    cudaGetSymbolAddress((void**)&p_lo1,g_lo1);
    cudaGetSymbolAddress((void**)&p_lo2, g_lo2);  cudaGetSymbolAddress((void**)&p_zt, g_zt);
    cudaGetSymbolAddress((void**)&p_mq,  g_mq);   cudaGetSymbolAddress((void**)&p_rq, g_rq);
    cudaGetSymbolAddress((void**)&p_mlv, g_mlv);  cudaGetSymbolAddress((void**)&p_rlv,g_rlv);
    cudaGetSymbolAddress((void**)&p_mw,  g_mw);   cudaGetSymbolAddress((void**)&p_rw, g_rw);
    cudaGetSymbolAddress((void**)&p_xh,  g_xh);   cudaGetSymbolAddress((void**)&p_xl, g_xl);
    cudaGetSymbolAddress((void**)&p_ath, g_ath);  cudaGetSymbolAddress((void**)&p_atl,g_atl);
    cudaGetSymbolAddress((void**)&p_zh,  g_zh);   cudaGetSymbolAddress((void**)&p_zl, g_zl);
    cudaGetSymbolAddress((void**)&p_wh,  g_wh);   cudaGetSymbolAddress((void**)&p_wl, g_wl);

    static cudaStream_t s1 = 0;
    static cudaEvent_t evQ = 0, evLV = 0, evATT = 0, evLANG = 0;
    if (!s1){
        cudaStreamCreateWithFlags(&s1, cudaStreamNonBlocking);
        cudaEventCreateWithFlags(&evQ,   cudaEventDisableTiming);
        cudaEventCreateWithFlags(&evLV,  cudaEventDisableTiming);
        cudaEventCreateWithFlags(&evATT, cudaEventDisableTiming);
        cudaEventCreateWithFlags(&evLANG,cudaEventDisableTiming);
        cudaFuncSetAttribute(tc_gemm, cudaFuncAttributeMaxDynamicSharedMemorySize, SMEMB);
    }

    dim3 blk256(256);
    // ---- stream 0: conversions + GEMM chain ----
    cvt_split<<<(int)(((size_t)Mm*Dd)/1024), blk256>>>(x, p_xh, p_xl);
    cvt_split<<<262144/1024, blk256>>>(w_q,   p_wh+WOFF_Q,   p_wl+WOFF_Q);
    cvt_split<<<262144/1024, blk256>>>(w_vis, p_wh+WOFF_VIS, p_wl+WOFF_VIS);
    cvt_split<<<393216/1024, blk256>>>(w_lv,  p_wh+WOFF_LV,  p_wl+WOFF_LV);
    cvt_split<<<262144/1024, blk256>>>(w_W,   p_wh+WOFF_W,   p_wl+WOFF_W);
    cvt_split<<<262144/1024, blk256>>>(w_mm,  p_wh+WOFF_MM,  p_wl+WOFF_MM);

    tc_gemm<<<dim3(Kch/128, Mm/128), blk256, SMEMB>>>(p_xh, p_xl, p_wh+WOFF_Q,   p_wl+WOFF_Q,   b_q,   p_q,   Kch, Dd, 0);
    cudaEventRecord(evQ, 0);
    tc_gemm<<<dim3(Dd/128,  Mm/128), blk256, SMEMB>>>(p_xh, p_xl, p_wh+WOFF_VIS, p_wl+WOFF_VIS, b_vis, p_vis, Dd,  Dd, 1);
    tc_gemm<<<dim3(CLd/128, Mm/128), blk256, SMEMB>>>(p_xh, p_xl, p_wh+WOFF_LV,  p_wl+WOFF_LV,  b_lv,  p_lv,  CLd, Dd, 0);
    cudaEventRecord(evLV, 0);

    // ---- stream 1: lang-side + attention chain (overlaps GEMMs) ----
    lang_conv_kernel<<<dim3(Bb, Kch/32), blk256, 0, s1>>>(l, w_k, b_k, lmask, p_k, Kch, 2);
    lang_conv_kernel<<<dim3(Bb, Vch/32), blk256, 0, s1>>>(l, w_v, b_v, lmask, p_v, Vch, 2);
    lang_conv_kernel<<<dim3(Bb, CLd/32), blk256, 0, s1>>>(l, w_langp, b_langp, lmask, p_lang, CLd, 1);
    cudaStreamWaitEvent(s1, evQ, 0);
    stats_kernel<<<dim3(Kch/32, Bb), dim3(32,16), 0, s1>>>(p_q, p_mq, p_rq, Kch);
    sim_kernel<<<dim3(HWd/1024, Bb*Hh), blk256, 0, s1>>>(lmask);
    latt_stats_kernel<<<Bb*Hh, dim3(32,32), 0, s1>>>();
    attout_kernel<<<dim3(HWd/256, Bb*Hh), blk256, 0, s1>>>();
    cudaEventRecord(evATT, s1);
    cudaStreamWaitEvent(s1, evLV, 0);
    stats_kernel<<<dim3(CLd/32, Bb), dim3(32,16), 0, s1>>>(p_lv, p_mlv, p_rlv, CLd);
    langout_part_kernel<<<dim3(Bb*Hh, SPL), blk256, 0, s1>>>();
    lo1_reduce_kernel<<<(Bb*CLd*NLd)/256, blk256, 0, s1>>>(lmask);
    lang_conv_kernel<<<dim3(Bb, CLd/32), blk256, 0, s1>>>(p_lo1, w_langW, b_langW, lmask, p_lo2, CLd, 8);
    ztmul_kernel<<<(Bb*CLd*NLd)/1024, blk256, 0, s1>>>();
    lang_conv_kernel<<<dim3(Bb, CLd/32), blk256, 0, s1>>>(p_zt, w_langmm, b_langmm, lmask,
                                                          out + (size_t)Mm*Vch, CLd, 1|4);
    cudaEventRecord(evLANG, s1);

    // ---- stream 0: tail GEMMs ----
    cudaStreamWaitEvent(0, evATT, 0);
    tc_gemm<<<dim3(Vch/128, Mm/128), blk256, SMEMB>>>(p_ath, p_atl, p_wh+WOFF_W, p_wl+WOFF_W, b_W, p_vo, Vch, Vch, 0);
    stats_kernel<<<dim3(Vch/32, Bb), dim3(32,16)>>>(p_vo, p_mw, p_rw, Vch);
    zmul_kernel<<<(int)(((size_t)Mm*Vch)/1024), blk256>>>();
    tc_gemm<<<dim3(Vch/128, Mm/128), blk256, SMEMB>>>(p_zh, p_zl, p_wh+WOFF_MM, p_wl+WOFF_MM, b_mm, out, Vch, Vch, 1);
    cudaStreamWaitEvent(0, evLANG, 0);
    (void)in_sizes; (void)n_in; (void)out_size;
}